// round 15
// baseline (speedup 1.0000x reference)
#include <cuda_runtime.h>
#include <math.h>
#include <cstdint>

#define NN 768
#define CNT 767.0f
#define NTL 24
#define EGRID 2400   // 300 tiles x 4 i-subs x 2 j-halves

typedef unsigned long long ull;

__device__ __align__(16) float g_embed0[NN*32];
__device__ __align__(16) float g_acc1[NN*32];
__device__ __align__(16) float g_e1[NN*64];
__device__ __align__(16) float g_acc2[NN*32];
__device__ float g_aggsum[160];
__device__ unsigned g_done;
__device__ __align__(16) float g_B1t[16*NN*2];
__device__ __align__(16) float g_P1t[16*NN*2];
__device__ __align__(16) float g_B2t[16*NN*2];
__device__ __align__(16) float g_P2t[16*NN*2];

__device__ __forceinline__ float silu_f(float x) {
    return __fdividef(x, 1.0f + __expf(-x));
}
__device__ __forceinline__ float silu_t(float x) {
    float xh = 0.5f * x, t;
    asm("tanh.approx.f32 %0, %1;" : "=f"(t) : "f"(xh));
    return fmaf(xh, t, xh);
}
__device__ __forceinline__ void upk2(ull v, float& lo, float& hi) {
    asm("mov.b64 {%0,%1}, %2;" : "=f"(lo), "=f"(hi) : "l"(v));
}
__device__ __forceinline__ uint32_t tf32c(float x) {
    uint32_t r; asm("cvt.rna.tf32.f32 %0, %1;" : "=r"(r) : "f"(x)); return r;
}
__device__ __forceinline__ void mma8(float* c,
    uint32_t a0, uint32_t a1, uint32_t a2, uint32_t a3, uint32_t b0, uint32_t b1)
{
    asm volatile("mma.sync.aligned.m16n8k8.row.col.f32.tf32.tf32.f32 "
        "{%0,%1,%2,%3}, {%4,%5,%6,%7}, {%8,%9}, {%0,%1,%2,%3};"
        : "+f"(c[0]), "+f"(c[1]), "+f"(c[2]), "+f"(c[3])
        : "r"(a0), "r"(a1), "r"(a2), "r"(a3), "r"(b0), "r"(b1));
}
__device__ __forceinline__ void jump4(float& s, float& c, float S4, float C4) {
    float ns = fmaf(s, C4, c*S4);
    float nc = fmaf(c, C4, -s*S4);
    s = ns; c = nc;
}

// ---------------- prep: embeddings + layer-1 projections (transposed) + reset ----
__global__ void prep_kernel(const float* __restrict__ embed_table,
                            const int*   __restrict__ charges,
                            const float* __restrict__ mp1_w0,
                            const float* __restrict__ mp1_b0)
{
    int gid = blockIdx.x * blockDim.x + threadIdx.x;
    int n = gid >> 5, j = gid & 31;
    int c = __ldg(&charges[n]);
    const float* er = embed_table + c * 32;
    g_embed0[n*32 + j] = __ldg(&er[j]);
    float a = __ldg(&mp1_b0[j]), b = 0.0f;
    #pragma unroll
    for (int k = 0; k < 32; k++) {
        float e = __ldg(&er[k]);
        a = fmaf(e, __ldg(&mp1_w0[k*32 + j]),        a);
        b = fmaf(e, __ldg(&mp1_w0[(32 + k)*32 + j]), b);
    }
    g_B1t[(j >> 1)*(2*NN) + n*2 + (j & 1)] = a;
    g_P1t[(j >> 1)*(2*NN) + n*2 + (j & 1)] = b;
    g_acc1[gid] = 0.0f;
    g_acc2[gid] = 0.0f;
    if (gid < 160) g_aggsum[gid] = 0.0f;
    if (gid == 0)  g_done = 0u;
}

// ---------------- edge kernel: tf32 mma.sync, warp = 1 i x 16 j ----------------
// W[k][f] read directly from wsrc (stride 32).
template <int L>
__global__ __launch_bounds__(256, 4) void edge_kernel(const float* __restrict__ nuclei,
                                                      const float* __restrict__ wsrc)
{
    __shared__ float sB[16*33];   // backward partials [16 local j][32 f], pad 33
    for (int e = threadIdx.x; e < 16*33; e += 256) sB[e] = 0.0f;
    __syncthreads();

    const ull* bt = reinterpret_cast<const ull*>((L == 0) ? g_B1t : g_B2t);
    const ull* pt = reinterpret_cast<const ull*>((L == 0) ? g_P1t : g_P2t);
    float*   accO = (L == 0) ? g_acc1 : g_acc2;

    const int b = blockIdx.x;
    int tile = b >> 3, isub = (b >> 1) & 3, jhalf = b & 1;
    int tI = 0, rem = tile;
    while (rem >= NTL - tI) { rem -= NTL - tI; tI++; }
    const int tJ = tI + rem;
    const bool diag = (tI == tJ);

    const int wid = threadIdx.x >> 5, ln = threadIdx.x & 31;
    const int qc = ln & 3;                 // l%4
    const int gp = ln >> 2;                // l/4
    const int i = tI*32 + isub*8 + wid;
    const int jbase = tJ*32 + jhalf*16;
    const int j0 = jbase + gp;             // row r0 = gp
    const int j1 = j0 + 8;                 // row r1 = gp+8

    const float ix = __ldg(&nuclei[i*3 + 0]);
    const float iy = __ldg(&nuclei[i*3 + 1]);
    const float iz = __ldg(&nuclei[i*3 + 2]);

    // geometry + chain state for both rows
    float pref0, mf0, ps0, pc0, S40, C40;
    float pref1, mf1, ps1, pc1, S41, C41;
    #pragma unroll
    for (int rr = 0; rr < 2; rr++) {
        int jr = rr ? j1 : j0;
        float dx = __ldg(&nuclei[jr*3 + 0]) - ix;
        float dy = __ldg(&nuclei[jr*3 + 1]) - iy;
        float dz = __ldg(&nuclei[jr*3 + 2]) - iz;
        float d2 = fmaf(dx, dx, fmaf(dy, dy, dz*dz));
        float mf = diag ? ((i < jr) ? 1.0f : 0.0f) : 1.0f;
        d2 = (i == jr) ? 1.0f : d2;
        float rsq = rsqrtf(d2);
        float th = d2 * rsq * 0.31415926535897931f;
        float s1, c1;
        __sincosf(th, &s1, &c1);
        float s2 = 2.0f*s1*c1,  c2 = fmaf(-2.0f*s1, s1, 1.0f);
        float s3 = s2*c1 + c2*s1, c3 = c2*c1 - s2*s1;
        float s4 = 2.0f*s2*c2,  c4 = fmaf(-2.0f*s2, s2, 1.0f);
        float ps = (qc == 0) ? s1 : (qc == 1) ? s2 : (qc == 2) ? s3 : s4;
        float pc = (qc == 0) ? c1 : (qc == 1) ? c2 : (qc == 2) ? c3 : c4;
        float pf = 0.44721359549995794f * rsq;
        if (rr == 0) { pref0 = pf; mf0 = mf; ps0 = ps; pc0 = pc; S40 = s4; C40 = c4; }
        else         { pref1 = pf; mf1 = mf; ps1 = ps; pc1 = pc; S41 = s4; C41 = c4; }
    }

    float cf[16];
    #pragma unroll
    for (int u = 0; u < 16; u++) cf[u] = 0.0f;

    // 4 k-steps of k=8; A sines advance by jump-of-4theta between captures
    #pragma unroll
    for (int s = 0; s < 4; s++) {
        uint32_t a0 = tf32c(ps0), a1 = tf32c(ps1);
        jump4(ps0, pc0, S40, C40);
        jump4(ps1, pc1, S41, C41);
        uint32_t a2 = tf32c(ps0), a3 = tf32c(ps1);
        jump4(ps0, pc0, S40, C40);
        jump4(ps1, pc1, S41, C41);
        const int k0 = qc + 8*s, k1 = k0 + 4;
        #pragma unroll
        for (int n = 0; n < 4; n++) {
            int col = gp + n*8;
            uint32_t b0 = tf32c(__ldg(&wsrc[k0*32 + col]));
            uint32_t b1 = tf32c(__ldg(&wsrc[k1*32 + col]));
            mma8(&cf[n*4], a0, a1, a2, a3, b0, b1);
        }
    }

    // epilogue per n-tile
    #pragma unroll
    for (int n = 0; n < 4; n++) {
        const int c = n*8 + qc*2;
        const int fi = (n*4 + qc)*NN;
        float bi0, bi1; upk2(__ldg(&bt[fi + i]), bi0, bi1);
        float pj00, pj01; upk2(__ldg(&pt[fi + j0]), pj00, pj01);
        float pj10, pj11; upk2(__ldg(&pt[fi + j1]), pj10, pj11);
        // forward: sender i
        float f00 = silu_t(fmaf(pref0, cf[n*4+0], bi0 + pj00)) * mf0;
        float f01 = silu_t(fmaf(pref0, cf[n*4+1], bi1 + pj01)) * mf0;
        float f10 = silu_t(fmaf(pref1, cf[n*4+2], bi0 + pj10)) * mf1;
        float f11 = silu_t(fmaf(pref1, cf[n*4+3], bi1 + pj11)) * mf1;
        float s0 = f00 + f10, s1 = f01 + f11;
        s0 += __shfl_xor_sync(0xffffffffu, s0, 4);
        s0 += __shfl_xor_sync(0xffffffffu, s0, 8);
        s0 += __shfl_xor_sync(0xffffffffu, s0, 16);
        s1 += __shfl_xor_sync(0xffffffffu, s1, 4);
        s1 += __shfl_xor_sync(0xffffffffu, s1, 8);
        s1 += __shfl_xor_sync(0xffffffffu, s1, 16);
        if (ln < 4) {
            atomicAdd(&accO[i*32 + c],     s0);
            atomicAdd(&accO[i*32 + c + 1], s1);
        }
        // backward: sender j -> smem tile
        float bj00, bj01; upk2(__ldg(&bt[fi + j0]), bj00, bj01);
        float bj10, bj11; upk2(__ldg(&bt[fi + j1]), bj10, bj11);
        float pi0, pi1;   upk2(__ldg(&pt[fi + i]),  pi0, pi1);
        float g00 = silu_t(fmaf(pref0, cf[n*4+0], bj00 + pi0)) * mf0;
        float g01 = silu_t(fmaf(pref0, cf[n*4+1], bj01 + pi1)) * mf0;
        float g10 = silu_t(fmaf(pref1, cf[n*4+2], bj10 + pi0)) * mf1;
        float g11 = silu_t(fmaf(pref1, cf[n*4+3], bj11 + pi1)) * mf1;
        atomicAdd(&sB[gp*33 + c],           g00);
        atomicAdd(&sB[gp*33 + c + 1],       g01);
        atomicAdd(&sB[(gp + 8)*33 + c],     g10);
        atomicAdd(&sB[(gp + 8)*33 + c + 1], g11);
    }

    __syncthreads();
    #pragma unroll
    for (int e = 0; e < 2; e++) {
        int idx = threadIdx.x + e*256;      // 0..511
        int row = idx >> 5, col = idx & 31;
        atomicAdd(&accO[(jbase + row)*32 + col], sB[row*33 + col]);
    }
}

// ---------------- node1 (verbatim from 74.5us build) ----------------
__global__ __launch_bounds__(64) void node1_kernel(
    const float* __restrict__ mp1_w1, const float* __restrict__ mp1_b1,
    const float* __restrict__ up1_w0, const float* __restrict__ up1_b0,
    const float* __restrict__ up1_w1, const float* __restrict__ up1_b1,
    const float* __restrict__ mp2_w0, const float* __restrict__ mp2_b0)
{
    int n = blockIdx.x, t = threadIdx.x;
    __shared__ float in64[64], h[64], e1[64], m[32];
    if (t < 32) {
        in64[t] = g_embed0[n*32 + t];
        m[t] = g_acc1[n*32 + t] * (1.0f / CNT);
    }
    __syncthreads();
    if (t < 32) {
        float a = mp1_b1[t];
        #pragma unroll
        for (int k = 0; k < 32; k++) a = fmaf(m[k], mp1_w1[k*32 + t], a);
        in64[32 + t] = a;
    }
    __syncthreads();
    {
        float a = up1_b0[t];
        #pragma unroll 8
        for (int k = 0; k < 64; k++) a = fmaf(in64[k], up1_w0[k*64 + t], a);
        h[t] = silu_f(a);
    }
    __syncthreads();
    {
        float a = up1_b1[t];
        #pragma unroll 8
        for (int k = 0; k < 64; k++) a = fmaf(h[k], up1_w1[k*64 + t], a);
        e1[t] = a;
        g_e1[n*64 + t] = a;
    }
    __syncthreads();
    if (t < 32) {
        float a = mp2_b0[t], bb = 0.0f;
        #pragma unroll 8
        for (int k = 0; k < 64; k++) {
            float e = e1[k];
            a  = fmaf(e, mp2_w0[k*32 + t],        a);
            bb = fmaf(e, mp2_w0[(64 + k)*32 + t], bb);
        }
        g_B2t[(t >> 1)*(2*NN) + n*2 + (t & 1)] = a;
        g_P2t[(t >> 1)*(2*NN) + n*2 + (t & 1)] = bb;
    }
}

// ---------------- node2 + fused global (verbatim) ----------------
__global__ __launch_bounds__(64) void node2_kernel(
    const int*   __restrict__ charges,
    const float* __restrict__ mp2_w1, const float* __restrict__ mp2_b1,
    const float* __restrict__ up2_w0, const float* __restrict__ up2_b0,
    const float* __restrict__ up2_w1, const float* __restrict__ up2_b1,
    const float* __restrict__ no_w0,  const float* __restrict__ no_b0,
    const float* __restrict__ no_w1,  const float* __restrict__ no_embed,
    const float* __restrict__ go_w0,  const float* __restrict__ go_b0,
    const float* __restrict__ go_w1,  const float* __restrict__ go_b1,
    float* __restrict__ out)
{
    int n = blockIdx.x, t = threadIdx.x;
    __shared__ float agg[160], in96[96], h[64], m[32], t3[3];
    __shared__ unsigned lastFlag;
    if (t < 32) {
        m[t] = g_acc2[n*32 + t] * (1.0f / CNT);
        agg[t] = g_embed0[n*32 + t];
    }
    float e1v = g_e1[n*64 + t];
    agg[32 + t] = e1v;
    in96[t] = e1v;
    __syncthreads();
    if (t < 32) {
        float a = mp2_b1[t];
        #pragma unroll
        for (int k = 0; k < 32; k++) a = fmaf(m[k], mp2_w1[k*32 + t], a);
        in96[64 + t] = a;
    }
    __syncthreads();
    {
        float a = up2_b0[t];
        #pragma unroll 8
        for (int k = 0; k < 96; k++) a = fmaf(in96[k], up2_w0[k*64 + t], a);
        h[t] = silu_f(a);
    }
    __syncthreads();
    {
        float a = up2_b1[t] + e1v;
        #pragma unroll 8
        for (int k = 0; k < 64; k++) a = fmaf(h[k], up2_w1[k*64 + t], a);
        agg[96 + t] = a;
    }
    __syncthreads();
    if (t < 3) {
        float a = no_b0[t];
        for (int k = 0; k < 160; k++) a = fmaf(agg[k], no_w0[k*3 + t], a);
        t3[t] = silu_f(a);
    }
    for (int i = t; i < 160; i += 64) atomicAdd(&g_aggsum[i], agg[i]);
    __syncthreads();
    if (t < 3) {
        int c = charges[n];
        float o = no_embed[c*3 + t];
        #pragma unroll
        for (int k = 0; k < 3; k++) o = fmaf(t3[k], no_w1[k*3 + t], o);
        out[n*3 + t] = o;
    }
    __threadfence();
    if (t == 0) lastFlag = (atomicAdd(&g_done, 1u) == (unsigned)(NN - 1)) ? 1u : 0u;
    __syncthreads();
    if (lastFlag) {
        __shared__ float red[64];
        float p = 0.0f;
        for (int i = t; i < 160; i += 64) p += g_aggsum[i] * go_w0[i];
        red[t] = p;
        __syncthreads();
        for (int sft = 32; sft > 0; sft >>= 1) {
            if (t < sft) red[t] += red[t + sft];
            __syncthreads();
        }
        if (t == 0) {
            float hh = silu_f(red[0] * (1.0f / (float)NN) + go_b0[0]);
            out[NN*3] = fmaf(hh, go_w1[0], go_b1[0]);
        }
    }
}

// ---------------- host ----------------
extern "C" void kernel_launch(void* const* d_in, const int* in_sizes, int n_in,
                              void* d_out, int out_size)
{
    const float* nuclei      = (const float*)d_in[0];
    const int*   charges     = (const int*)  d_in[1];
    const float* embed_table = (const float*)d_in[3];
    const float* mp1_w0 = (const float*)d_in[4];
    const float* mp1_b0 = (const float*)d_in[5];
    const float* mp1_w1 = (const float*)d_in[6];
    const float* mp1_b1 = (const float*)d_in[7];
    const float* up1_w0 = (const float*)d_in[8];
    const float* up1_b0 = (const float*)d_in[9];
    const float* up1_w1 = (const float*)d_in[10];
    const float* up1_b1 = (const float*)d_in[11];
    const float* mp2_w0 = (const float*)d_in[12];
    const float* mp2_b0 = (const float*)d_in[13];
    const float* mp2_w1 = (const float*)d_in[14];
    const float* mp2_b1 = (const float*)d_in[15];
    const float* up2_w0 = (const float*)d_in[16];
    const float* up2_b0 = (const float*)d_in[17];
    const float* up2_w1 = (const float*)d_in[18];
    const float* up2_b1 = (const float*)d_in[19];
    const float* no_w0  = (const float*)d_in[20];
    const float* no_b0  = (const float*)d_in[21];
    const float* no_w1  = (const float*)d_in[22];
    const float* no_emb = (const float*)d_in[23];
    const float* go_w0  = (const float*)d_in[24];
    const float* go_b0  = (const float*)d_in[25];
    const float* go_w1  = (const float*)d_in[26];
    const float* go_b1  = (const float*)d_in[27];
    float* out = (float*)d_out;

    prep_kernel<<<NN*32/256, 256>>>(embed_table, charges, mp1_w0, mp1_b0);
    edge_kernel<0><<<EGRID, 256>>>(nuclei, mp1_w0 + 64*32);
    node1_kernel<<<NN, 64>>>(mp1_w1, mp1_b1, up1_w0, up1_b0, up1_w1, up1_b1, mp2_w0, mp2_b0);
    edge_kernel<1><<<EGRID, 256>>>(nuclei, mp2_w0 + 128*32);
    node2_kernel<<<NN, 64>>>(charges, mp2_w1, mp2_b1, up2_w0, up2_b0, up2_w1, up2_b1,
                             no_w0, no_b0, no_w1, no_emb,
                             go_w0, go_b0, go_w1, go_b1, out);
}

// round 16
// speedup vs baseline: 1.4127x; 1.4127x over previous
#include <cuda_runtime.h>
#include <math.h>
#include <cstdint>

#define NN 768
#define CNT 767.0f
#define NTL 24
#define EGRID 2400   // 300 tiles x 4 i-subs x 2 j-halves

typedef unsigned long long ull;

__device__ __align__(16) float g_embed0[NN*32];
__device__ __align__(16) float g_acc1[NN*32];
__device__ __align__(16) float g_e1[NN*64];
__device__ __align__(16) float g_acc2[NN*32];
__device__ float g_aggsum[160];
__device__ unsigned g_done;
__device__ __align__(16) float g_B1t[16*NN*2];
__device__ __align__(16) float g_P1t[16*NN*2];
__device__ __align__(16) float g_B2t[16*NN*2];
__device__ __align__(16) float g_P2t[16*NN*2];

__device__ __forceinline__ float silu_f(float x) {
    return __fdividef(x, 1.0f + __expf(-x));
}
__device__ __forceinline__ float silu_t(float x) {
    float xh = 0.5f * x, t;
    asm("tanh.approx.f32 %0, %1;" : "=f"(t) : "f"(xh));
    return fmaf(xh, t, xh);
}
__device__ __forceinline__ void upk2(ull v, float& lo, float& hi) {
    asm("mov.b64 {%0,%1}, %2;" : "=f"(lo), "=f"(hi) : "l"(v));
}
__device__ __forceinline__ uint32_t tf32c(float x) {
    uint32_t r; asm("cvt.rna.tf32.f32 %0, %1;" : "=r"(r) : "f"(x)); return r;
}
__device__ __forceinline__ void mma8(float* c,
    uint32_t a0, uint32_t a1, uint32_t a2, uint32_t a3, uint32_t b0, uint32_t b1)
{
    asm volatile("mma.sync.aligned.m16n8k8.row.col.f32.tf32.tf32.f32 "
        "{%0,%1,%2,%3}, {%4,%5,%6,%7}, {%8,%9}, {%0,%1,%2,%3};"
        : "+f"(c[0]), "+f"(c[1]), "+f"(c[2]), "+f"(c[3])
        : "r"(a0), "r"(a1), "r"(a2), "r"(a3), "r"(b0), "r"(b1));
}
__device__ __forceinline__ void jump4(float& s, float& c, float S4, float C4) {
    float ns = fmaf(s, C4, c*S4);
    float nc = fmaf(c, C4, -s*S4);
    s = ns; c = nc;
}

// ---------------- prep ----------------
__global__ void prep_kernel(const float* __restrict__ embed_table,
                            const int*   __restrict__ charges,
                            const float* __restrict__ mp1_w0,
                            const float* __restrict__ mp1_b0)
{
    int gid = blockIdx.x * blockDim.x + threadIdx.x;
    int n = gid >> 5, j = gid & 31;
    int c = __ldg(&charges[n]);
    const float* er = embed_table + c * 32;
    g_embed0[n*32 + j] = __ldg(&er[j]);
    float a = __ldg(&mp1_b0[j]), b = 0.0f;
    #pragma unroll
    for (int k = 0; k < 32; k++) {
        float e = __ldg(&er[k]);
        a = fmaf(e, __ldg(&mp1_w0[k*32 + j]),        a);
        b = fmaf(e, __ldg(&mp1_w0[(32 + k)*32 + j]), b);
    }
    g_B1t[(j >> 1)*(2*NN) + n*2 + (j & 1)] = a;
    g_P1t[(j >> 1)*(2*NN) + n*2 + (j & 1)] = b;
    g_acc1[gid] = 0.0f;
    g_acc2[gid] = 0.0f;
    if (gid < 160) g_aggsum[gid] = 0.0f;
    if (gid == 0)  g_done = 0u;
}

// ---------------- edge kernel: tf32 mma.sync + staged epilogue ----------------
template <int L>
__global__ __launch_bounds__(256, 4) void edge_kernel(const float* __restrict__ nuclei,
                                                      const float* __restrict__ wsrc)
{
    __shared__ __align__(16) float sBW[8][16][36];      // per-warp backward tiles
    __shared__ __align__(16) ull sPj[16][17], sBj[16][17];
    __shared__ __align__(16) ull sPi[16][9],  sBi[16][9];

    const ull* bt = reinterpret_cast<const ull*>((L == 0) ? g_B1t : g_B2t);
    const ull* pt = reinterpret_cast<const ull*>((L == 0) ? g_P1t : g_P2t);
    float*   accO = (L == 0) ? g_acc1 : g_acc2;

    const int b = blockIdx.x;
    int tile = b >> 3, isub = (b >> 1) & 3, jhalf = b & 1;
    int tI = 0, rem = tile;
    while (rem >= NTL - tI) { rem -= NTL - tI; tI++; }
    const int tJ = tI + rem;
    const bool diag = (tI == tJ);

    const int wid = threadIdx.x >> 5, ln = threadIdx.x & 31;
    const int qc = ln & 3;
    const int gp = ln >> 2;
    const int ibase = tI*32 + isub*8;
    const int i = ibase + wid;
    const int jbase = tJ*32 + jhalf*16;
    const int j0 = jbase + gp;
    const int j1 = j0 + 8;

    // stage node projections (coalesced, once per block)
    {
        int f2 = threadIdx.x >> 4, jj = threadIdx.x & 15;
        sPj[f2][jj] = __ldg(&pt[f2*NN + jbase + jj]);
        sBj[f2][jj] = __ldg(&bt[f2*NN + jbase + jj]);
        if (threadIdx.x < 128) {
            int f = threadIdx.x >> 3, ii = threadIdx.x & 7;
            sPi[f][ii] = __ldg(&pt[f*NN + ibase + ii]);
        } else {
            int x = threadIdx.x - 128, f = x >> 3, ii = x & 7;
            sBi[f][ii] = __ldg(&bt[f*NN + ibase + ii]);
        }
    }

    const float ix = __ldg(&nuclei[i*3 + 0]);
    const float iy = __ldg(&nuclei[i*3 + 1]);
    const float iz = __ldg(&nuclei[i*3 + 2]);

    // geometry + sine chain state for both j rows
    float pref0, mf0, ps0, pc0, S40, C40;
    float pref1, mf1, ps1, pc1, S41, C41;
    #pragma unroll
    for (int rr = 0; rr < 2; rr++) {
        int jr = rr ? j1 : j0;
        float dx = __ldg(&nuclei[jr*3 + 0]) - ix;
        float dy = __ldg(&nuclei[jr*3 + 1]) - iy;
        float dz = __ldg(&nuclei[jr*3 + 2]) - iz;
        float d2 = fmaf(dx, dx, fmaf(dy, dy, dz*dz));
        float mf = diag ? ((i < jr) ? 1.0f : 0.0f) : 1.0f;
        d2 = (i == jr) ? 1.0f : d2;
        float rsq = rsqrtf(d2);
        float th = d2 * rsq * 0.31415926535897931f;
        float s1, c1;
        __sincosf(th, &s1, &c1);
        float s2 = 2.0f*s1*c1,  c2 = fmaf(-2.0f*s1, s1, 1.0f);
        float s3 = s2*c1 + c2*s1, c3 = c2*c1 - s2*s1;
        float s4 = 2.0f*s2*c2,  c4 = fmaf(-2.0f*s2, s2, 1.0f);
        float ps = (qc == 0) ? s1 : (qc == 1) ? s2 : (qc == 2) ? s3 : s4;
        float pc = (qc == 0) ? c1 : (qc == 1) ? c2 : (qc == 2) ? c3 : c4;
        float pf = 0.44721359549995794f * rsq;
        if (rr == 0) { pref0 = pf; mf0 = mf; ps0 = ps; pc0 = pc; S40 = s4; C40 = c4; }
        else         { pref1 = pf; mf1 = mf; ps1 = ps; pc1 = pc; S41 = s4; C41 = c4; }
    }

    float cf[16];
    #pragma unroll
    for (int u = 0; u < 16; u++) cf[u] = 0.0f;

    #pragma unroll
    for (int s = 0; s < 4; s++) {
        uint32_t a0 = tf32c(ps0), a1 = tf32c(ps1);
        jump4(ps0, pc0, S40, C40);
        jump4(ps1, pc1, S41, C41);
        uint32_t a2 = tf32c(ps0), a3 = tf32c(ps1);
        jump4(ps0, pc0, S40, C40);
        jump4(ps1, pc1, S41, C41);
        const int k0 = qc + 8*s, k1 = k0 + 4;
        #pragma unroll
        for (int n = 0; n < 4; n++) {
            int col = gp + n*8;
            uint32_t b0 = tf32c(__ldg(&wsrc[k0*32 + col]));
            uint32_t b1 = tf32c(__ldg(&wsrc[k1*32 + col]));
            mma8(&cf[n*4], a0, a1, a2, a3, b0, b1);
        }
    }

    __syncthreads();   // staged projections ready

    // epilogue per n-tile, all projections from smem
    #pragma unroll
    for (int n = 0; n < 4; n++) {
        const int c = n*8 + qc*2;
        const int f2 = n*4 + qc;
        float bi0, bi1;   upk2(sBi[f2][wid], bi0, bi1);
        float pj00, pj01; upk2(sPj[f2][gp],     pj00, pj01);
        float pj10, pj11; upk2(sPj[f2][gp + 8], pj10, pj11);
        // forward: sender i -> acc[i]
        float f00 = silu_t(fmaf(pref0, cf[n*4+0], bi0 + pj00)) * mf0;
        float f01 = silu_t(fmaf(pref0, cf[n*4+1], bi1 + pj01)) * mf0;
        float f10 = silu_t(fmaf(pref1, cf[n*4+2], bi0 + pj10)) * mf1;
        float f11 = silu_t(fmaf(pref1, cf[n*4+3], bi1 + pj11)) * mf1;
        float s0 = f00 + f10, s1 = f01 + f11;
        s0 += __shfl_xor_sync(0xffffffffu, s0, 4);
        s0 += __shfl_xor_sync(0xffffffffu, s0, 8);
        s0 += __shfl_xor_sync(0xffffffffu, s0, 16);
        s1 += __shfl_xor_sync(0xffffffffu, s1, 4);
        s1 += __shfl_xor_sync(0xffffffffu, s1, 8);
        s1 += __shfl_xor_sync(0xffffffffu, s1, 16);
        if (ln < 4) {
            atomicAdd(&accO[i*32 + c],     s0);
            atomicAdd(&accO[i*32 + c + 1], s1);
        }
        // backward: sender j -> per-warp smem tile (no atomics)
        float bj00, bj01; upk2(sBj[f2][gp],     bj00, bj01);
        float bj10, bj11; upk2(sBj[f2][gp + 8], bj10, bj11);
        float pi0, pi1;   upk2(sPi[f2][wid],    pi0, pi1);
        float g00 = silu_t(fmaf(pref0, cf[n*4+0], bj00 + pi0)) * mf0;
        float g01 = silu_t(fmaf(pref0, cf[n*4+1], bj01 + pi1)) * mf0;
        float g10 = silu_t(fmaf(pref1, cf[n*4+2], bj10 + pi0)) * mf1;
        float g11 = silu_t(fmaf(pref1, cf[n*4+3], bj11 + pi1)) * mf1;
        *reinterpret_cast<float2*>(&sBW[wid][gp][c])     = make_float2(g00, g01);
        *reinterpret_cast<float2*>(&sBW[wid][gp + 8][c]) = make_float2(g10, g11);
    }

    __syncthreads();
    // block backward reduce: 512 (j,f) cells, 2 per thread
    #pragma unroll
    for (int e = 0; e < 2; e++) {
        int idx = threadIdx.x + e*256;
        int row = idx >> 5, col = idx & 31;
        float a = sBW[0][row][col];
        #pragma unroll
        for (int w = 1; w < 8; w++) a += sBW[w][row][col];
        atomicAdd(&accO[(jbase + row)*32 + col], a);
    }
}

// ---------------- node1 (verbatim) ----------------
__global__ __launch_bounds__(64) void node1_kernel(
    const float* __restrict__ mp1_w1, const float* __restrict__ mp1_b1,
    const float* __restrict__ up1_w0, const float* __restrict__ up1_b0,
    const float* __restrict__ up1_w1, const float* __restrict__ up1_b1,
    const float* __restrict__ mp2_w0, const float* __restrict__ mp2_b0)
{
    int n = blockIdx.x, t = threadIdx.x;
    __shared__ float in64[64], h[64], e1[64], m[32];
    if (t < 32) {
        in64[t] = g_embed0[n*32 + t];
        m[t] = g_acc1[n*32 + t] * (1.0f / CNT);
    }
    __syncthreads();
    if (t < 32) {
        float a = mp1_b1[t];
        #pragma unroll
        for (int k = 0; k < 32; k++) a = fmaf(m[k], mp1_w1[k*32 + t], a);
        in64[32 + t] = a;
    }
    __syncthreads();
    {
        float a = up1_b0[t];
        #pragma unroll 8
        for (int k = 0; k < 64; k++) a = fmaf(in64[k], up1_w0[k*64 + t], a);
        h[t] = silu_f(a);
    }
    __syncthreads();
    {
        float a = up1_b1[t];
        #pragma unroll 8
        for (int k = 0; k < 64; k++) a = fmaf(h[k], up1_w1[k*64 + t], a);
        e1[t] = a;
        g_e1[n*64 + t] = a;
    }
    __syncthreads();
    if (t < 32) {
        float a = mp2_b0[t], bb = 0.0f;
        #pragma unroll 8
        for (int k = 0; k < 64; k++) {
            float e = e1[k];
            a  = fmaf(e, mp2_w0[k*32 + t],        a);
            bb = fmaf(e, mp2_w0[(64 + k)*32 + t], bb);
        }
        g_B2t[(t >> 1)*(2*NN) + n*2 + (t & 1)] = a;
        g_P2t[(t >> 1)*(2*NN) + n*2 + (t & 1)] = bb;
    }
}

// ---------------- node2 + fused global (verbatim) ----------------
__global__ __launch_bounds__(64) void node2_kernel(
    const int*   __restrict__ charges,
    const float* __restrict__ mp2_w1, const float* __restrict__ mp2_b1,
    const float* __restrict__ up2_w0, const float* __restrict__ up2_b0,
    const float* __restrict__ up2_w1, const float* __restrict__ up2_b1,
    const float* __restrict__ no_w0,  const float* __restrict__ no_b0,
    const float* __restrict__ no_w1,  const float* __restrict__ no_embed,
    const float* __restrict__ go_w0,  const float* __restrict__ go_b0,
    const float* __restrict__ go_w1,  const float* __restrict__ go_b1,
    float* __restrict__ out)
{
    int n = blockIdx.x, t = threadIdx.x;
    __shared__ float agg[160], in96[96], h[64], m[32], t3[3];
    __shared__ unsigned lastFlag;
    if (t < 32) {
        m[t] = g_acc2[n*32 + t] * (1.0f / CNT);
        agg[t] = g_embed0[n*32 + t];
    }
    float e1v = g_e1[n*64 + t];
    agg[32 + t] = e1v;
    in96[t] = e1v;
    __syncthreads();
    if (t < 32) {
        float a = mp2_b1[t];
        #pragma unroll
        for (int k = 0; k < 32; k++) a = fmaf(m[k], mp2_w1[k*32 + t], a);
        in96[64 + t] = a;
    }
    __syncthreads();
    {
        float a = up2_b0[t];
        #pragma unroll 8
        for (int k = 0; k < 96; k++) a = fmaf(in96[k], up2_w0[k*64 + t], a);
        h[t] = silu_f(a);
    }
    __syncthreads();
    {
        float a = up2_b1[t] + e1v;
        #pragma unroll 8
        for (int k = 0; k < 64; k++) a = fmaf(h[k], up2_w1[k*64 + t], a);
        agg[96 + t] = a;
    }
    __syncthreads();
    if (t < 3) {
        float a = no_b0[t];
        for (int k = 0; k < 160; k++) a = fmaf(agg[k], no_w0[k*3 + t], a);
        t3[t] = silu_f(a);
    }
    for (int i = t; i < 160; i += 64) atomicAdd(&g_aggsum[i], agg[i]);
    __syncthreads();
    if (t < 3) {
        int c = charges[n];
        float o = no_embed[c*3 + t];
        #pragma unroll
        for (int k = 0; k < 3; k++) o = fmaf(t3[k], no_w1[k*3 + t], o);
        out[n*3 + t] = o;
    }
    __threadfence();
    if (t == 0) lastFlag = (atomicAdd(&g_done, 1u) == (unsigned)(NN - 1)) ? 1u : 0u;
    __syncthreads();
    if (lastFlag) {
        __shared__ float red[64];
        float p = 0.0f;
        for (int i = t; i < 160; i += 64) p += g_aggsum[i] * go_w0[i];
        red[t] = p;
        __syncthreads();
        for (int sft = 32; sft > 0; sft >>= 1) {
            if (t < sft) red[t] += red[t + sft];
            __syncthreads();
        }
        if (t == 0) {
            float hh = silu_f(red[0] * (1.0f / (float)NN) + go_b0[0]);
            out[NN*3] = fmaf(hh, go_w1[0], go_b1[0]);
        }
    }
}

// ---------------- host ----------------
extern "C" void kernel_launch(void* const* d_in, const int* in_sizes, int n_in,
                              void* d_out, int out_size)
{
    const float* nuclei      = (const float*)d_in[0];
    const int*   charges     = (const int*)  d_in[1];
    const float* embed_table = (const float*)d_in[3];
    const float* mp1_w0 = (const float*)d_in[4];
    const float* mp1_b0 = (const float*)d_in[5];
    const float* mp1_w1 = (const float*)d_in[6];
    const float* mp1_b1 = (const float*)d_in[7];
    const float* up1_w0 = (const float*)d_in[8];
    const float* up1_b0 = (const float*)d_in[9];
    const float* up1_w1 = (const float*)d_in[10];
    const float* up1_b1 = (const float*)d_in[11];
    const float* mp2_w0 = (const float*)d_in[12];
    const float* mp2_b0 = (const float*)d_in[13];
    const float* mp2_w1 = (const float*)d_in[14];
    const float* mp2_b1 = (const float*)d_in[15];
    const float* up2_w0 = (const float*)d_in[16];
    const float* up2_b0 = (const float*)d_in[17];
    const float* up2_w1 = (const float*)d_in[18];
    const float* up2_b1 = (const float*)d_in[19];
    const float* no_w0  = (const float*)d_in[20];
    const float* no_b0  = (const float*)d_in[21];
    const float* no_w1  = (const float*)d_in[22];
    const float* no_emb = (const float*)d_in[23];
    const float* go_w0  = (const float*)d_in[24];
    const float* go_b0  = (const float*)d_in[25];
    const float* go_w1  = (const float*)d_in[26];
    const float* go_b1  = (const float*)d_in[27];
    float* out = (float*)d_out;

    prep_kernel<<<NN*32/256, 256>>>(embed_table, charges, mp1_w0, mp1_b0);
    edge_kernel<0><<<EGRID, 256>>>(nuclei, mp1_w0 + 64*32);
    node1_kernel<<<NN, 64>>>(mp1_w1, mp1_b1, up1_w0, up1_b0, up1_w1, up1_b1, mp2_w0, mp2_b0);
    edge_kernel<1><<<EGRID, 256>>>(nuclei, mp2_w0 + 128*32);
    node2_kernel<<<NN, 64>>>(charges, mp2_w1, mp2_b1, up2_w0, up2_b0, up2_w1, up2_b1,
                             no_w0, no_b0, no_w1, no_emb,
                             go_w0, go_b0, go_w1, go_b1, out);
}

// round 17
// speedup vs baseline: 1.6202x; 1.1469x over previous
#include <cuda_runtime.h>
#include <math.h>
#include <cstdint>

#define NN 768
#define CNT 767.0f
#define NTL 24
#define EGRID 2400   // 300 tiles x 4 i-subs x 2 j-halves

typedef unsigned long long ull;

__device__ __align__(16) float g_embed0[NN*32];
__device__ __align__(16) float g_acc1[NN*32];
__device__ __align__(16) float g_e1[NN*64];
__device__ __align__(16) float g_acc2[NN*32];
__device__ float g_aggsum[160];
__device__ unsigned g_done;
__device__ __align__(16) float g_B1t[16*NN*2];
__device__ __align__(16) float g_P1t[16*NN*2];
__device__ __align__(16) float g_B2t[16*NN*2];
__device__ __align__(16) float g_P2t[16*NN*2];

__device__ __forceinline__ float silu_f(float x) {
    return __fdividef(x, 1.0f + __expf(-x));
}
__device__ __forceinline__ float silu_t(float x) {
    float xh = 0.5f * x, t;
    asm("tanh.approx.f32 %0, %1;" : "=f"(t) : "f"(xh));
    return fmaf(xh, t, xh);
}
__device__ __forceinline__ void upk2(ull v, float& lo, float& hi) {
    asm("mov.b64 {%0,%1}, %2;" : "=f"(lo), "=f"(hi) : "l"(v));
}
__device__ __forceinline__ uint32_t tf32c(float x) {
    uint32_t r; asm("cvt.rna.tf32.f32 %0, %1;" : "=r"(r) : "f"(x)); return r;
}
__device__ __forceinline__ void mma8(float* c,
    uint32_t a0, uint32_t a1, uint32_t a2, uint32_t a3, uint32_t b0, uint32_t b1)
{
    asm volatile("mma.sync.aligned.m16n8k8.row.col.f32.tf32.tf32.f32 "
        "{%0,%1,%2,%3}, {%4,%5,%6,%7}, {%8,%9}, {%0,%1,%2,%3};"
        : "+f"(c[0]), "+f"(c[1]), "+f"(c[2]), "+f"(c[3])
        : "r"(a0), "r"(a1), "r"(a2), "r"(a3), "r"(b0), "r"(b1));
}
__device__ __forceinline__ void jump4(float& s, float& c, float S4, float C4) {
    float ns = fmaf(s, C4, c*S4);
    float nc = fmaf(c, C4, -s*S4);
    s = ns; c = nc;
}

// ---------------- prep ----------------
__global__ void prep_kernel(const float* __restrict__ embed_table,
                            const int*   __restrict__ charges,
                            const float* __restrict__ mp1_w0,
                            const float* __restrict__ mp1_b0)
{
    int gid = blockIdx.x * blockDim.x + threadIdx.x;
    int n = gid >> 5, j = gid & 31;
    int c = __ldg(&charges[n]);
    const float* er = embed_table + c * 32;
    g_embed0[n*32 + j] = __ldg(&er[j]);
    float a = __ldg(&mp1_b0[j]), b = 0.0f;
    #pragma unroll
    for (int k = 0; k < 32; k++) {
        float e = __ldg(&er[k]);
        a = fmaf(e, __ldg(&mp1_w0[k*32 + j]),        a);
        b = fmaf(e, __ldg(&mp1_w0[(32 + k)*32 + j]), b);
    }
    g_B1t[(j >> 1)*(2*NN) + n*2 + (j & 1)] = a;
    g_P1t[(j >> 1)*(2*NN) + n*2 + (j & 1)] = b;
    g_acc1[gid] = 0.0f;
    g_acc2[gid] = 0.0f;
    if (gid < 160) g_aggsum[gid] = 0.0f;
    if (gid == 0)  g_done = 0u;
}

// ---------------- edge kernel: tf32 mma.sync + conflict-free epilogue ----------------
template <int L>
__global__ __launch_bounds__(256, 4) void edge_kernel(const float* __restrict__ nuclei,
                                                      const float* __restrict__ wsrc)
{
    __shared__ __align__(16) float sBW[8][16][40];       // 40-stride: conflict-free f2 stores
    __shared__ __align__(16) ull sPj[16][20], sBj[16][20];   // [j][f2], 20-ull stride
    __shared__ __align__(16) ull sPi[16][9],  sBi[16][9];    // [f2][i]

    const ull* bt = reinterpret_cast<const ull*>((L == 0) ? g_B1t : g_B2t);
    const ull* pt = reinterpret_cast<const ull*>((L == 0) ? g_P1t : g_P2t);
    float*   accO = (L == 0) ? g_acc1 : g_acc2;

    const int b = blockIdx.x;
    int tile = b >> 3, isub = (b >> 1) & 3, jhalf = b & 1;
    int tI = 0, rem = tile;
    while (rem >= NTL - tI) { rem -= NTL - tI; tI++; }
    const int tJ = tI + rem;
    const bool diag = (tI == tJ);

    const int wid = threadIdx.x >> 5, ln = threadIdx.x & 31;
    const int qc = ln & 3;
    const int gp = ln >> 2;
    const int ibase = tI*32 + isub*8;
    const int i = ibase + wid;
    const int jbase = tJ*32 + jhalf*16;
    const int j0 = jbase + gp;
    const int j1 = j0 + 8;

    // stage node projections (coalesced gmem, once per block)
    {
        int f2 = threadIdx.x >> 4, jj = threadIdx.x & 15;
        sPj[jj][f2] = __ldg(&pt[f2*NN + jbase + jj]);
        sBj[jj][f2] = __ldg(&bt[f2*NN + jbase + jj]);
        if (threadIdx.x < 128) {
            int f = threadIdx.x >> 3, ii = threadIdx.x & 7;
            sPi[f][ii] = __ldg(&pt[f*NN + ibase + ii]);
        } else {
            int x = threadIdx.x - 128, f = x >> 3, ii = x & 7;
            sBi[f][ii] = __ldg(&bt[f*NN + ibase + ii]);
        }
    }

    const float ix = __ldg(&nuclei[i*3 + 0]);
    const float iy = __ldg(&nuclei[i*3 + 1]);
    const float iz = __ldg(&nuclei[i*3 + 2]);

    // geometry + sine chain state for both j rows
    float pref0, mf0, ps0, pc0, S40, C40;
    float pref1, mf1, ps1, pc1, S41, C41;
    #pragma unroll
    for (int rr = 0; rr < 2; rr++) {
        int jr = rr ? j1 : j0;
        float dx = __ldg(&nuclei[jr*3 + 0]) - ix;
        float dy = __ldg(&nuclei[jr*3 + 1]) - iy;
        float dz = __ldg(&nuclei[jr*3 + 2]) - iz;
        float d2 = fmaf(dx, dx, fmaf(dy, dy, dz*dz));
        float mf = diag ? ((i < jr) ? 1.0f : 0.0f) : 1.0f;
        d2 = (i == jr) ? 1.0f : d2;
        float rsq = rsqrtf(d2);
        float th = d2 * rsq * 0.31415926535897931f;
        float s1, c1;
        __sincosf(th, &s1, &c1);
        float s2 = 2.0f*s1*c1,  c2 = fmaf(-2.0f*s1, s1, 1.0f);
        float s3 = s2*c1 + c2*s1, c3 = c2*c1 - s2*s1;
        float s4 = 2.0f*s2*c2,  c4 = fmaf(-2.0f*s2, s2, 1.0f);
        float ps = (qc == 0) ? s1 : (qc == 1) ? s2 : (qc == 2) ? s3 : s4;
        float pc = (qc == 0) ? c1 : (qc == 1) ? c2 : (qc == 2) ? c3 : c4;
        float pf = 0.44721359549995794f * rsq;
        if (rr == 0) { pref0 = pf; mf0 = mf; ps0 = ps; pc0 = pc; S40 = s4; C40 = c4; }
        else         { pref1 = pf; mf1 = mf; ps1 = ps; pc1 = pc; S41 = s4; C41 = c4; }
    }

    float cf[16];
    #pragma unroll
    for (int u = 0; u < 16; u++) cf[u] = 0.0f;

    #pragma unroll
    for (int s = 0; s < 4; s++) {
        uint32_t a0 = tf32c(ps0), a1 = tf32c(ps1);
        jump4(ps0, pc0, S40, C40);
        jump4(ps1, pc1, S41, C41);
        uint32_t a2 = tf32c(ps0), a3 = tf32c(ps1);
        jump4(ps0, pc0, S40, C40);
        jump4(ps1, pc1, S41, C41);
        const int k0 = qc + 8*s, k1 = k0 + 4;
        #pragma unroll
        for (int n = 0; n < 4; n++) {
            int col = gp + n*8;
            uint32_t b0 = tf32c(__ldg(&wsrc[k0*32 + col]));
            uint32_t b1 = tf32c(__ldg(&wsrc[k1*32 + col]));
            mma8(&cf[n*4], a0, a1, a2, a3, b0, b1);
        }
    }

    __syncthreads();   // staged projections ready

    // epilogue per n-tile (conflict-free smem)
    #pragma unroll
    for (int n = 0; n < 4; n++) {
        const int c = n*8 + qc*2;
        const int f2 = n*4 + qc;
        float bi0, bi1;   upk2(sBi[f2][wid], bi0, bi1);
        float pj00, pj01; upk2(sPj[gp][f2],     pj00, pj01);
        float pj10, pj11; upk2(sPj[gp + 8][f2], pj10, pj11);
        // forward: sender i -> acc[i]
        float f00 = silu_t(fmaf(pref0, cf[n*4+0], bi0 + pj00)) * mf0;
        float f01 = silu_t(fmaf(pref0, cf[n*4+1], bi1 + pj01)) * mf0;
        float f10 = silu_t(fmaf(pref1, cf[n*4+2], bi0 + pj10)) * mf1;
        float f11 = silu_t(fmaf(pref1, cf[n*4+3], bi1 + pj11)) * mf1;
        float s0 = f00 + f10, s1 = f01 + f11;
        s0 += __shfl_xor_sync(0xffffffffu, s0, 4);
        s0 += __shfl_xor_sync(0xffffffffu, s0, 8);
        s0 += __shfl_xor_sync(0xffffffffu, s0, 16);
        s1 += __shfl_xor_sync(0xffffffffu, s1, 4);
        s1 += __shfl_xor_sync(0xffffffffu, s1, 8);
        s1 += __shfl_xor_sync(0xffffffffu, s1, 16);
        if (ln < 4) {
            atomicAdd(&accO[i*32 + c],     s0);
            atomicAdd(&accO[i*32 + c + 1], s1);
        }
        // backward: sender j -> per-warp smem tile (no atomics)
        float bj00, bj01; upk2(sBj[gp][f2],     bj00, bj01);
        float bj10, bj11; upk2(sBj[gp + 8][f2], bj10, bj11);
        float pi0, pi1;   upk2(sPi[f2][wid],    pi0, pi1);
        float g00 = silu_t(fmaf(pref0, cf[n*4+0], bj00 + pi0)) * mf0;
        float g01 = silu_t(fmaf(pref0, cf[n*4+1], bj01 + pi1)) * mf0;
        float g10 = silu_t(fmaf(pref1, cf[n*4+2], bj10 + pi0)) * mf1;
        float g11 = silu_t(fmaf(pref1, cf[n*4+3], bj11 + pi1)) * mf1;
        *reinterpret_cast<float2*>(&sBW[wid][gp][c])     = make_float2(g00, g01);
        *reinterpret_cast<float2*>(&sBW[wid][gp + 8][c]) = make_float2(g10, g11);
    }

    __syncthreads();
    // block backward reduce: 512 (j,f) cells, 2 per thread
    #pragma unroll
    for (int e = 0; e < 2; e++) {
        int idx = threadIdx.x + e*256;
        int row = idx >> 5, col = idx & 31;
        float a = sBW[0][row][col];
        #pragma unroll
        for (int w = 1; w < 8; w++) a += sBW[w][row][col];
        atomicAdd(&accO[(jbase + row)*32 + col], a);
    }
}

// ---------------- node1 (verbatim) ----------------
__global__ __launch_bounds__(64) void node1_kernel(
    const float* __restrict__ mp1_w1, const float* __restrict__ mp1_b1,
    const float* __restrict__ up1_w0, const float* __restrict__ up1_b0,
    const float* __restrict__ up1_w1, const float* __restrict__ up1_b1,
    const float* __restrict__ mp2_w0, const float* __restrict__ mp2_b0)
{
    int n = blockIdx.x, t = threadIdx.x;
    __shared__ float in64[64], h[64], e1[64], m[32];
    if (t < 32) {
        in64[t] = g_embed0[n*32 + t];
        m[t] = g_acc1[n*32 + t] * (1.0f / CNT);
    }
    __syncthreads();
    if (t < 32) {
        float a = mp1_b1[t];
        #pragma unroll
        for (int k = 0; k < 32; k++) a = fmaf(m[k], mp1_w1[k*32 + t], a);
        in64[32 + t] = a;
    }
    __syncthreads();
    {
        float a = up1_b0[t];
        #pragma unroll 8
        for (int k = 0; k < 64; k++) a = fmaf(in64[k], up1_w0[k*64 + t], a);
        h[t] = silu_f(a);
    }
    __syncthreads();
    {
        float a = up1_b1[t];
        #pragma unroll 8
        for (int k = 0; k < 64; k++) a = fmaf(h[k], up1_w1[k*64 + t], a);
        e1[t] = a;
        g_e1[n*64 + t] = a;
    }
    __syncthreads();
    if (t < 32) {
        float a = mp2_b0[t], bb = 0.0f;
        #pragma unroll 8
        for (int k = 0; k < 64; k++) {
            float e = e1[k];
            a  = fmaf(e, mp2_w0[k*32 + t],        a);
            bb = fmaf(e, mp2_w0[(64 + k)*32 + t], bb);
        }
        g_B2t[(t >> 1)*(2*NN) + n*2 + (t & 1)] = a;
        g_P2t[(t >> 1)*(2*NN) + n*2 + (t & 1)] = bb;
    }
}

// ---------------- node2 + fused global (verbatim) ----------------
__global__ __launch_bounds__(64) void node2_kernel(
    const int*   __restrict__ charges,
    const float* __restrict__ mp2_w1, const float* __restrict__ mp2_b1,
    const float* __restrict__ up2_w0, const float* __restrict__ up2_b0,
    const float* __restrict__ up2_w1, const float* __restrict__ up2_b1,
    const float* __restrict__ no_w0,  const float* __restrict__ no_b0,
    const float* __restrict__ no_w1,  const float* __restrict__ no_embed,
    const float* __restrict__ go_w0,  const float* __restrict__ go_b0,
    const float* __restrict__ go_w1,  const float* __restrict__ go_b1,
    float* __restrict__ out)
{
    int n = blockIdx.x, t = threadIdx.x;
    __shared__ float agg[160], in96[96], h[64], m[32], t3[3];
    __shared__ unsigned lastFlag;
    if (t < 32) {
        m[t] = g_acc2[n*32 + t] * (1.0f / CNT);
        agg[t] = g_embed0[n*32 + t];
    }
    float e1v = g_e1[n*64 + t];
    agg[32 + t] = e1v;
    in96[t] = e1v;
    __syncthreads();
    if (t < 32) {
        float a = mp2_b1[t];
        #pragma unroll
        for (int k = 0; k < 32; k++) a = fmaf(m[k], mp2_w1[k*32 + t], a);
        in96[64 + t] = a;
    }
    __syncthreads();
    {
        float a = up2_b0[t];
        #pragma unroll 8
        for (int k = 0; k < 96; k++) a = fmaf(in96[k], up2_w0[k*64 + t], a);
        h[t] = silu_f(a);
    }
    __syncthreads();
    {
        float a = up2_b1[t] + e1v;
        #pragma unroll 8
        for (int k = 0; k < 64; k++) a = fmaf(h[k], up2_w1[k*64 + t], a);
        agg[96 + t] = a;
    }
    __syncthreads();
    if (t < 3) {
        float a = no_b0[t];
        for (int k = 0; k < 160; k++) a = fmaf(agg[k], no_w0[k*3 + t], a);
        t3[t] = silu_f(a);
    }
    for (int i = t; i < 160; i += 64) atomicAdd(&g_aggsum[i], agg[i]);
    __syncthreads();
    if (t < 3) {
        int c = charges[n];
        float o = no_embed[c*3 + t];
        #pragma unroll
        for (int k = 0; k < 3; k++) o = fmaf(t3[k], no_w1[k*3 + t], o);
        out[n*3 + t] = o;
    }
    __threadfence();
    if (t == 0) lastFlag = (atomicAdd(&g_done, 1u) == (unsigned)(NN - 1)) ? 1u : 0u;
    __syncthreads();
    if (lastFlag) {
        __shared__ float red[64];
        float p = 0.0f;
        for (int i = t; i < 160; i += 64) p += g_aggsum[i] * go_w0[i];
        red[t] = p;
        __syncthreads();
        for (int sft = 32; sft > 0; sft >>= 1) {
            if (t < sft) red[t] += red[t + sft];
            __syncthreads();
        }
        if (t == 0) {
            float hh = silu_f(red[0] * (1.0f / (float)NN) + go_b0[0]);
            out[NN*3] = fmaf(hh, go_w1[0], go_b1[0]);
        }
    }
}

// ---------------- host ----------------
extern "C" void kernel_launch(void* const* d_in, const int* in_sizes, int n_in,
                              void* d_out, int out_size)
{
    const float* nuclei      = (const float*)d_in[0];
    const int*   charges     = (const int*)  d_in[1];
    const float* embed_table = (const float*)d_in[3];
    const float* mp1_w0 = (const float*)d_in[4];
    const float* mp1_b0 = (const float*)d_in[5];
    const float* mp1_w1 = (const float*)d_in[6];
    const float* mp1_b1 = (const float*)d_in[7];
    const float* up1_w0 = (const float*)d_in[8];
    const float* up1_b0 = (const float*)d_in[9];
    const float* up1_w1 = (const float*)d_in[10];
    const float* up1_b1 = (const float*)d_in[11];
    const float* mp2_w0 = (const float*)d_in[12];
    const float* mp2_b0 = (const float*)d_in[13];
    const float* mp2_w1 = (const float*)d_in[14];
    const float* mp2_b1 = (const float*)d_in[15];
    const float* up2_w0 = (const float*)d_in[16];
    const float* up2_b0 = (const float*)d_in[17];
    const float* up2_w1 = (const float*)d_in[18];
    const float* up2_b1 = (const float*)d_in[19];
    const float* no_w0  = (const float*)d_in[20];
    const float* no_b0  = (const float*)d_in[21];
    const float* no_w1  = (const float*)d_in[22];
    const float* no_emb = (const float*)d_in[23];
    const float* go_w0  = (const float*)d_in[24];
    const float* go_b0  = (const float*)d_in[25];
    const float* go_w1  = (const float*)d_in[26];
    const float* go_b1  = (const float*)d_in[27];
    float* out = (float*)d_out;

    prep_kernel<<<NN*32/256, 256>>>(embed_table, charges, mp1_w0, mp1_b0);
    edge_kernel<0><<<EGRID, 256>>>(nuclei, mp1_w0 + 64*32);
    node1_kernel<<<NN, 64>>>(mp1_w1, mp1_b1, up1_w0, up1_b0, up1_w1, up1_b1, mp2_w0, mp2_b0);
    edge_kernel<1><<<EGRID, 256>>>(nuclei, mp2_w0 + 128*32);
    node2_kernel<<<NN, 64>>>(charges, mp2_w1, mp2_b1, up2_w0, up2_b0, up2_w1, up2_b1,
                             no_w0, no_b0, no_w1, no_emb,
                             go_w0, go_b0, go_w1, go_b1, out);
}